// round 4
// baseline (speedup 1.0000x reference)
#include <cuda_runtime.h>
#include <cuda_bf16.h>

// LoRA: out[b,s,o] = scaling * sum_r ( sum_i x[b,s,i] * A[r,i] ) * B[o,r]
// x: [4, 8192, 1024] f32   A: [4, 1024] f32   B: [1024, 4] f32   scaling = 0.25
//
// Pure HBM-streaming problem (256 MB mandatory traffic, ~0.5 GFLOP).
// One warp per token row; A and B staged in shared memory once per block
// (B transposed to rank-major to keep the epilogue LDS conflict-free).

#define LORA_NROWS   (4 * 8192)   // 32768 token rows
#define LORA_NF4     256          // 1024 features / 4 (float4 granularity)
#define LORA_BLOCK   256
#define LORA_WPB     8            // warps (rows) per block per iteration
#define LORA_GRID    1024
#define LORA_SCALE   0.25f

__global__ __launch_bounds__(LORA_BLOCK, 7)
void lora_fused_kernel(const float* __restrict__ x,
                       const float* __restrict__ A,
                       const float* __restrict__ B,
                       float* __restrict__ out)
{
    __shared__ float sA[4 * 1024];   // rank-major, same as global A layout
    __shared__ float sBt[4 * 1024];  // TRANSPOSED: sBt[r*1024 + o] = B[o*4 + r]

    const int tid = threadIdx.x;

    // ---- Stage A (direct float4 copy) and B (transpose) into smem ----
    {
        const float4* A4  = reinterpret_cast<const float4*>(A);
        float4*       sA4 = reinterpret_cast<float4*>(sA);
        #pragma unroll
        for (int i = 0; i < 4; i++)
            sA4[tid + i * 256] = A4[tid + i * 256];

        const float4* B4 = reinterpret_cast<const float4*>(B);  // one float4 = one B row
        #pragma unroll
        for (int i = 0; i < 4; i++) {
            int o = tid + i * 256;
            float4 b = B4[o];
            sBt[0 * 1024 + o] = b.x;
            sBt[1 * 1024 + o] = b.y;
            sBt[2 * 1024 + o] = b.z;
            sBt[3 * 1024 + o] = b.w;
        }
    }
    __syncthreads();

    const int lane = tid & 31;
    const int wid  = tid >> 5;

    const float4* sA4c = reinterpret_cast<const float4*>(sA);
    const float4* sB0  = reinterpret_cast<const float4*>(sBt);
    const float4* sB1  = reinterpret_cast<const float4*>(sBt + 1024);
    const float4* sB2  = reinterpret_cast<const float4*>(sBt + 2048);
    const float4* sB3  = reinterpret_cast<const float4*>(sBt + 3072);

    for (int row = blockIdx.x * LORA_WPB + wid; row < LORA_NROWS;
         row += LORA_GRID * LORA_WPB) {

        const float4* xr = reinterpret_cast<const float4*>(x) + (size_t)row * LORA_NF4;

        // ---- Pass 1: 4 rank dot-products over the 1024-feature row ----
        float s0 = 0.f, s1 = 0.f, s2 = 0.f, s3 = 0.f;
        #pragma unroll
        for (int j = 0; j < 8; j++) {
            int idx = j * 32 + lane;                 // coalesced float4 index
            float4 xv = xr[idx];
            float4 a0 = sA4c[0 * 256 + idx];
            float4 a1 = sA4c[1 * 256 + idx];
            float4 a2 = sA4c[2 * 256 + idx];
            float4 a3 = sA4c[3 * 256 + idx];
            s0 = fmaf(xv.x, a0.x, fmaf(xv.y, a0.y, fmaf(xv.z, a0.z, fmaf(xv.w, a0.w, s0))));
            s1 = fmaf(xv.x, a1.x, fmaf(xv.y, a1.y, fmaf(xv.z, a1.z, fmaf(xv.w, a1.w, s1))));
            s2 = fmaf(xv.x, a2.x, fmaf(xv.y, a2.y, fmaf(xv.z, a2.z, fmaf(xv.w, a2.w, s2))));
            s3 = fmaf(xv.x, a3.x, fmaf(xv.y, a3.y, fmaf(xv.z, a3.z, fmaf(xv.w, a3.w, s3))));
        }

        // ---- Warp butterfly reduce: every lane ends with the full row sums ----
        #pragma unroll
        for (int off = 16; off > 0; off >>= 1) {
            s0 += __shfl_xor_sync(0xffffffffu, s0, off);
            s1 += __shfl_xor_sync(0xffffffffu, s1, off);
            s2 += __shfl_xor_sync(0xffffffffu, s2, off);
            s3 += __shfl_xor_sync(0xffffffffu, s3, off);
        }
        s0 *= LORA_SCALE; s1 *= LORA_SCALE; s2 *= LORA_SCALE; s3 *= LORA_SCALE;

        // ---- Pass 2: expand to 1024 outputs via rank-major B (conflict-free LDS) ----
        float4* orow = reinterpret_cast<float4*>(out) + (size_t)row * LORA_NF4;
        #pragma unroll
        for (int j = 0; j < 8; j++) {
            int idx = j * 32 + lane;
            float4 b0 = sB0[idx];
            float4 b1 = sB1[idx];
            float4 b2 = sB2[idx];
            float4 b3 = sB3[idx];
            float4 o;
            o.x = fmaf(s0, b0.x, fmaf(s1, b1.x, fmaf(s2, b2.x, s3 * b3.x)));
            o.y = fmaf(s0, b0.y, fmaf(s1, b1.y, fmaf(s2, b2.y, s3 * b3.y)));
            o.z = fmaf(s0, b0.z, fmaf(s1, b1.z, fmaf(s2, b2.z, s3 * b3.z)));
            o.w = fmaf(s0, b0.w, fmaf(s1, b1.w, fmaf(s2, b2.w, s3 * b3.w)));
            orow[idx] = o;
        }
    }
}

extern "C" void kernel_launch(void* const* d_in, const int* in_sizes, int n_in,
                              void* d_out, int out_size)
{
    const float* x = (const float*)d_in[0];   // [4, 8192, 1024]
    const float* A = (const float*)d_in[1];   // [4, 1024]
    const float* B = (const float*)d_in[2];   // [1024, 4]
    float* out     = (float*)d_out;           // [4, 8192, 1024]

    lora_fused_kernel<<<LORA_GRID, LORA_BLOCK>>>(x, A, B, out);
}

// round 5
// speedup vs baseline: 3.3268x; 3.3268x over previous
#include <cuda_runtime.h>
#include <cuda_bf16.h>

// LoRA: out[b,s,o] = scaling * sum_r ( sum_i x[b,s,i] * A[r,i] ) * B[o,r]
// x: [4, 8192, 1024] f32   A: [4, 1024] f32   B: [1024, 4] f32   scaling = 0.25
//
// HBM-streaming problem: 256 MB mandatory traffic -> ~40-50 us floor.
// R4 lesson: __launch_bounds__(256,7) capped regs at 32, killing load
// batching (MLP~1) and exposing full DRAM latency per load. This version
// removes the reg clamp and explicitly prefetches the whole 4 KB row slice
// (8 x float4 per lane) into registers before consuming it.

#define LORA_NROWS   (4 * 8192)   // 32768 token rows
#define LORA_NF4     256          // 1024 features / 4 (float4 granularity)
#define LORA_BLOCK   256
#define LORA_WPB     8            // warps (rows) per block per iteration
#define LORA_GRID    1024
#define LORA_SCALE   0.25f

__global__ __launch_bounds__(LORA_BLOCK)
void lora_fused_kernel(const float* __restrict__ x,
                       const float* __restrict__ A,
                       const float* __restrict__ B,
                       float* __restrict__ out)
{
    __shared__ float sA[4 * 1024];   // rank-major, same as global A layout
    __shared__ float sBt[4 * 1024];  // TRANSPOSED: sBt[r*1024 + o] = B[o*4 + r]

    const int tid = threadIdx.x;

    // ---- Stage A (direct float4 copy) and B (transpose) into smem ----
    {
        const float4* A4  = reinterpret_cast<const float4*>(A);
        float4*       sA4 = reinterpret_cast<float4*>(sA);
        #pragma unroll
        for (int i = 0; i < 4; i++)
            sA4[tid + i * 256] = A4[tid + i * 256];

        const float4* B4 = reinterpret_cast<const float4*>(B);  // one float4 = one B row
        #pragma unroll
        for (int i = 0; i < 4; i++) {
            int o = tid + i * 256;
            float4 b = B4[o];
            sBt[0 * 1024 + o] = b.x;
            sBt[1 * 1024 + o] = b.y;
            sBt[2 * 1024 + o] = b.z;
            sBt[3 * 1024 + o] = b.w;
        }
    }
    __syncthreads();

    const int lane = tid & 31;
    const int wid  = tid >> 5;

    const float4* sA4c = reinterpret_cast<const float4*>(sA);
    const float4* sB0  = reinterpret_cast<const float4*>(sBt);
    const float4* sB1  = reinterpret_cast<const float4*>(sBt + 1024);
    const float4* sB2  = reinterpret_cast<const float4*>(sBt + 2048);
    const float4* sB3  = reinterpret_cast<const float4*>(sBt + 3072);

    for (int row = blockIdx.x * LORA_WPB + wid; row < LORA_NROWS;
         row += LORA_GRID * LORA_WPB) {

        const float4* xr = reinterpret_cast<const float4*>(x) + (size_t)row * LORA_NF4;

        // ---- Prefetch the entire row slice: 8 independent LDG.128 (MLP=8) ----
        float4 xv[8];
        #pragma unroll
        for (int j = 0; j < 8; j++)
            xv[j] = xr[j * 32 + lane];

        // ---- Pass 1: 4 rank dot-products over the 1024-feature row ----
        float s0 = 0.f, s1 = 0.f, s2 = 0.f, s3 = 0.f;
        #pragma unroll
        for (int j = 0; j < 8; j++) {
            int idx = j * 32 + lane;
            float4 a0 = sA4c[0 * 256 + idx];
            float4 a1 = sA4c[1 * 256 + idx];
            float4 a2 = sA4c[2 * 256 + idx];
            float4 a3 = sA4c[3 * 256 + idx];
            s0 = fmaf(xv[j].x, a0.x, fmaf(xv[j].y, a0.y, fmaf(xv[j].z, a0.z, fmaf(xv[j].w, a0.w, s0))));
            s1 = fmaf(xv[j].x, a1.x, fmaf(xv[j].y, a1.y, fmaf(xv[j].z, a1.z, fmaf(xv[j].w, a1.w, s1))));
            s2 = fmaf(xv[j].x, a2.x, fmaf(xv[j].y, a2.y, fmaf(xv[j].z, a2.z, fmaf(xv[j].w, a2.w, s2))));
            s3 = fmaf(xv[j].x, a3.x, fmaf(xv[j].y, a3.y, fmaf(xv[j].z, a3.z, fmaf(xv[j].w, a3.w, s3))));
        }

        // ---- Warp butterfly reduce: every lane ends with the full row sums ----
        #pragma unroll
        for (int off = 16; off > 0; off >>= 1) {
            s0 += __shfl_xor_sync(0xffffffffu, s0, off);
            s1 += __shfl_xor_sync(0xffffffffu, s1, off);
            s2 += __shfl_xor_sync(0xffffffffu, s2, off);
            s3 += __shfl_xor_sync(0xffffffffu, s3, off);
        }
        s0 *= LORA_SCALE; s1 *= LORA_SCALE; s2 *= LORA_SCALE; s3 *= LORA_SCALE;

        // ---- Pass 2: expand to 1024 outputs via rank-major B (conflict-free LDS) ----
        float4* orow = reinterpret_cast<float4*>(out) + (size_t)row * LORA_NF4;
        #pragma unroll
        for (int j = 0; j < 8; j++) {
            int idx = j * 32 + lane;
            float4 b0 = sB0[idx];
            float4 b1 = sB1[idx];
            float4 b2 = sB2[idx];
            float4 b3 = sB3[idx];
            float4 o;
            o.x = fmaf(s0, b0.x, fmaf(s1, b1.x, fmaf(s2, b2.x, s3 * b3.x)));
            o.y = fmaf(s0, b0.y, fmaf(s1, b1.y, fmaf(s2, b2.y, s3 * b3.y)));
            o.z = fmaf(s0, b0.z, fmaf(s1, b1.z, fmaf(s2, b2.z, s3 * b3.z)));
            o.w = fmaf(s0, b0.w, fmaf(s1, b1.w, fmaf(s2, b2.w, s3 * b3.w)));
            orow[idx] = o;
        }
    }
}

extern "C" void kernel_launch(void* const* d_in, const int* in_sizes, int n_in,
                              void* d_out, int out_size)
{
    const float* x = (const float*)d_in[0];   // [4, 8192, 1024]
    const float* A = (const float*)d_in[1];   // [4, 1024]
    const float* B = (const float*)d_in[2];   // [1024, 4]
    float* out     = (float*)d_out;           // [4, 8192, 1024]

    lora_fused_kernel<<<LORA_GRID, LORA_BLOCK>>>(x, A, B, out);
}

// round 6
// speedup vs baseline: 4.6468x; 1.3968x over previous
#include <cuda_runtime.h>
#include <cuda_bf16.h>

// LoRA: out[b,s,o] = scaling * sum_r ( sum_i x[b,s,i] * A[r,i] ) * B[o,r]
// x: [4, 8192, 1024] f32   A: [4, 1024] f32   B: [1024, 4] f32   scaling = 0.25
//
// HBM-streaming problem: 256 MB mandatory traffic -> ~40-50 us floor.
// R4: reg cap 32 killed MLP (232us). R5: no cap -> 174 regs, 1 CTA/SM,
// occ 11.5%, DRAM 43% (69.7us). This round: budget ~84 regs via
// __launch_bounds__(256,3) -- keeps the 8-deep LDG.128 prefetch (true live
// set ~66 regs) while tripling resident warps to ~24/SM so load phases of
// different warps overlap and DRAM stays saturated.

#define LORA_NROWS   (4 * 8192)   // 32768 token rows
#define LORA_NF4     256          // 1024 features / 4 (float4 granularity)
#define LORA_BLOCK   256
#define LORA_WPB     8            // warps (rows) per block per iteration
#define LORA_GRID    1024
#define LORA_SCALE   0.25f

__global__ __launch_bounds__(LORA_BLOCK, 3)
void lora_fused_kernel(const float* __restrict__ x,
                       const float* __restrict__ A,
                       const float* __restrict__ B,
                       float* __restrict__ out)
{
    __shared__ float sA[4 * 1024];   // rank-major, same as global A layout
    __shared__ float sBt[4 * 1024];  // TRANSPOSED: sBt[r*1024 + o] = B[o*4 + r]

    const int tid = threadIdx.x;

    // ---- Stage A (direct float4 copy) and B (transpose) into smem ----
    {
        const float4* A4  = reinterpret_cast<const float4*>(A);
        float4*       sA4 = reinterpret_cast<float4*>(sA);
        #pragma unroll
        for (int i = 0; i < 4; i++)
            sA4[tid + i * 256] = A4[tid + i * 256];

        const float4* B4 = reinterpret_cast<const float4*>(B);  // one float4 = one B row
        #pragma unroll
        for (int i = 0; i < 4; i++) {
            int o = tid + i * 256;
            float4 b = B4[o];
            sBt[0 * 1024 + o] = b.x;
            sBt[1 * 1024 + o] = b.y;
            sBt[2 * 1024 + o] = b.z;
            sBt[3 * 1024 + o] = b.w;
        }
    }
    __syncthreads();

    const int lane = tid & 31;
    const int wid  = tid >> 5;

    const float4* sA4c = reinterpret_cast<const float4*>(sA);
    const float4* sB0  = reinterpret_cast<const float4*>(sBt);
    const float4* sB1  = reinterpret_cast<const float4*>(sBt + 1024);
    const float4* sB2  = reinterpret_cast<const float4*>(sBt + 2048);
    const float4* sB3  = reinterpret_cast<const float4*>(sBt + 3072);

    for (int row = blockIdx.x * LORA_WPB + wid; row < LORA_NROWS;
         row += LORA_GRID * LORA_WPB) {

        const float4* xr = reinterpret_cast<const float4*>(x) + (size_t)row * LORA_NF4;

        // ---- Prefetch the entire row slice: 8 independent LDG.128 (MLP=8).
        //      Streaming hint: x is read exactly once.
        float4 xv[8];
        #pragma unroll
        for (int j = 0; j < 8; j++)
            xv[j] = __ldcs(&xr[j * 32 + lane]);

        // ---- Pass 1: 4 rank dot-products over the 1024-feature row ----
        float s0 = 0.f, s1 = 0.f, s2 = 0.f, s3 = 0.f;
        #pragma unroll
        for (int j = 0; j < 8; j++) {
            int idx = j * 32 + lane;
            float4 a0 = sA4c[0 * 256 + idx];
            float4 a1 = sA4c[1 * 256 + idx];
            float4 a2 = sA4c[2 * 256 + idx];
            float4 a3 = sA4c[3 * 256 + idx];
            s0 = fmaf(xv[j].x, a0.x, fmaf(xv[j].y, a0.y, fmaf(xv[j].z, a0.z, fmaf(xv[j].w, a0.w, s0))));
            s1 = fmaf(xv[j].x, a1.x, fmaf(xv[j].y, a1.y, fmaf(xv[j].z, a1.z, fmaf(xv[j].w, a1.w, s1))));
            s2 = fmaf(xv[j].x, a2.x, fmaf(xv[j].y, a2.y, fmaf(xv[j].z, a2.z, fmaf(xv[j].w, a2.w, s2))));
            s3 = fmaf(xv[j].x, a3.x, fmaf(xv[j].y, a3.y, fmaf(xv[j].z, a3.z, fmaf(xv[j].w, a3.w, s3))));
        }

        // ---- Warp butterfly reduce: every lane ends with the full row sums ----
        #pragma unroll
        for (int off = 16; off > 0; off >>= 1) {
            s0 += __shfl_xor_sync(0xffffffffu, s0, off);
            s1 += __shfl_xor_sync(0xffffffffu, s1, off);
            s2 += __shfl_xor_sync(0xffffffffu, s2, off);
            s3 += __shfl_xor_sync(0xffffffffu, s3, off);
        }
        s0 *= LORA_SCALE; s1 *= LORA_SCALE; s2 *= LORA_SCALE; s3 *= LORA_SCALE;

        // ---- Pass 2: expand to 1024 outputs via rank-major B (conflict-free LDS).
        //      Streaming store: out is written once, never re-read.
        float4* orow = reinterpret_cast<float4*>(out) + (size_t)row * LORA_NF4;
        #pragma unroll
        for (int j = 0; j < 8; j++) {
            int idx = j * 32 + lane;
            float4 b0 = sB0[idx];
            float4 b1 = sB1[idx];
            float4 b2 = sB2[idx];
            float4 b3 = sB3[idx];
            float4 o;
            o.x = fmaf(s0, b0.x, fmaf(s1, b1.x, fmaf(s2, b2.x, s3 * b3.x)));
            o.y = fmaf(s0, b0.y, fmaf(s1, b1.y, fmaf(s2, b2.y, s3 * b3.y)));
            o.z = fmaf(s0, b0.z, fmaf(s1, b1.z, fmaf(s2, b2.z, s3 * b3.z)));
            o.w = fmaf(s0, b0.w, fmaf(s1, b1.w, fmaf(s2, b2.w, s3 * b3.w)));
            __stcs(&orow[idx], o);
        }
    }
}

extern "C" void kernel_launch(void* const* d_in, const int* in_sizes, int n_in,
                              void* d_out, int out_size)
{
    const float* x = (const float*)d_in[0];   // [4, 8192, 1024]
    const float* A = (const float*)d_in[1];   // [4, 1024]
    const float* B = (const float*)d_in[2];   // [1024, 4]
    float* out     = (float*)d_out;           // [4, 8192, 1024]

    lora_fused_kernel<<<LORA_GRID, LORA_BLOCK>>>(x, A, B, out);
}

// round 7
// speedup vs baseline: 4.8881x; 1.0519x over previous
#include <cuda_runtime.h>
#include <cuda_bf16.h>

// LoRA: out[b,s,o] = scaling * sum_r ( sum_i x[b,s,i] * A[r,i] ) * B[o,r]
// x: [4, 8192, 1024] f32   A: [4, 1024] f32   B: [1024, 4] f32   scaling = 0.25
//
// Evolution: R4 reg-cap-32 -> MLP 1 (232us). R5 no cap -> 174 regs/occ 11% (69us).
// R6 cap 84 -> occ 32%, but L1tex 82.6% saturated by 64 LDS.128/row (49.9us).
// R7: A/B smem tiles are row-invariant -> process 2 rows per warp iteration,
// sharing every LDS between both rows. LSU ops/row: 80 -> 48. Per-warp MLP
// doubles to 16 LDG.128. Reg budget 128 (2 CTAs/SM).

#define LORA_NROWS   (4 * 8192)   // 32768 token rows
#define LORA_NF4     256          // 1024 features / 4 (float4 granularity)
#define LORA_BLOCK   256
#define LORA_WARPS   8
#define LORA_GRID    1024
#define LORA_NWARPS  (LORA_GRID * LORA_WARPS)      // 8192 warps
#define LORA_PAIRS   (LORA_NROWS / 2)              // 16384 row-pairs
#define LORA_SCALE   0.25f

__global__ __launch_bounds__(LORA_BLOCK, 2)
void lora_fused_kernel(const float* __restrict__ x,
                       const float* __restrict__ A,
                       const float* __restrict__ B,
                       float* __restrict__ out)
{
    __shared__ float sA[4 * 1024];   // rank-major, same as global A layout
    __shared__ float sBt[4 * 1024];  // TRANSPOSED: sBt[r*1024 + o] = B[o*4 + r]

    const int tid = threadIdx.x;

    // ---- Stage A (direct float4 copy) and B (transpose) into smem ----
    {
        const float4* A4  = reinterpret_cast<const float4*>(A);
        float4*       sA4 = reinterpret_cast<float4*>(sA);
        #pragma unroll
        for (int i = 0; i < 4; i++)
            sA4[tid + i * 256] = A4[tid + i * 256];

        const float4* B4 = reinterpret_cast<const float4*>(B);  // one float4 = one B row
        #pragma unroll
        for (int i = 0; i < 4; i++) {
            int o = tid + i * 256;
            float4 b = B4[o];
            sBt[0 * 1024 + o] = b.x;
            sBt[1 * 1024 + o] = b.y;
            sBt[2 * 1024 + o] = b.z;
            sBt[3 * 1024 + o] = b.w;
        }
    }
    __syncthreads();

    const int lane = tid & 31;
    const int wid  = tid >> 5;
    const int warp_global = blockIdx.x * LORA_WARPS + wid;

    const float4* sA4c = reinterpret_cast<const float4*>(sA);
    const float4* sB0  = reinterpret_cast<const float4*>(sBt);
    const float4* sB1  = reinterpret_cast<const float4*>(sBt + 1024);
    const float4* sB2  = reinterpret_cast<const float4*>(sBt + 2048);
    const float4* sB3  = reinterpret_cast<const float4*>(sBt + 3072);

    // Each warp handles 2 consecutive rows per iteration; 16384 pairs total.
    for (int pair = warp_global; pair < LORA_PAIRS; pair += LORA_NWARPS) {
        const size_t row0 = (size_t)pair * 2;

        const float4* xr0 = reinterpret_cast<const float4*>(x) + row0 * LORA_NF4;
        const float4* xr1 = xr0 + LORA_NF4;

        // ---- Prefetch both rows: 16 independent LDG.128 (MLP=16) ----
        float4 xv0[8], xv1[8];
        #pragma unroll
        for (int j = 0; j < 8; j++) xv0[j] = __ldcs(&xr0[j * 32 + lane]);
        #pragma unroll
        for (int j = 0; j < 8; j++) xv1[j] = __ldcs(&xr1[j * 32 + lane]);

        // ---- Pass 1: rank dot-products, A tile shared between both rows ----
        float p0 = 0.f, p1 = 0.f, p2 = 0.f, p3 = 0.f;   // row0
        float q0 = 0.f, q1 = 0.f, q2 = 0.f, q3 = 0.f;   // row1
        #pragma unroll
        for (int j = 0; j < 8; j++) {
            int idx = j * 32 + lane;
            float4 a0 = sA4c[0 * 256 + idx];
            float4 a1 = sA4c[1 * 256 + idx];
            float4 a2 = sA4c[2 * 256 + idx];
            float4 a3 = sA4c[3 * 256 + idx];
            p0 = fmaf(xv0[j].x, a0.x, fmaf(xv0[j].y, a0.y, fmaf(xv0[j].z, a0.z, fmaf(xv0[j].w, a0.w, p0))));
            p1 = fmaf(xv0[j].x, a1.x, fmaf(xv0[j].y, a1.y, fmaf(xv0[j].z, a1.z, fmaf(xv0[j].w, a1.w, p1))));
            p2 = fmaf(xv0[j].x, a2.x, fmaf(xv0[j].y, a2.y, fmaf(xv0[j].z, a2.z, fmaf(xv0[j].w, a2.w, p2))));
            p3 = fmaf(xv0[j].x, a3.x, fmaf(xv0[j].y, a3.y, fmaf(xv0[j].z, a3.z, fmaf(xv0[j].w, a3.w, p3))));
            q0 = fmaf(xv1[j].x, a0.x, fmaf(xv1[j].y, a0.y, fmaf(xv1[j].z, a0.z, fmaf(xv1[j].w, a0.w, q0))));
            q1 = fmaf(xv1[j].x, a1.x, fmaf(xv1[j].y, a1.y, fmaf(xv1[j].z, a1.z, fmaf(xv1[j].w, a1.w, q1))));
            q2 = fmaf(xv1[j].x, a2.x, fmaf(xv1[j].y, a2.y, fmaf(xv1[j].z, a2.z, fmaf(xv1[j].w, a2.w, q2))));
            q3 = fmaf(xv1[j].x, a3.x, fmaf(xv1[j].y, a3.y, fmaf(xv1[j].z, a3.z, fmaf(xv1[j].w, a3.w, q3))));
        }

        // ---- Warp butterfly reduce (all 8 sums) ----
        #pragma unroll
        for (int off = 16; off > 0; off >>= 1) {
            p0 += __shfl_xor_sync(0xffffffffu, p0, off);
            p1 += __shfl_xor_sync(0xffffffffu, p1, off);
            p2 += __shfl_xor_sync(0xffffffffu, p2, off);
            p3 += __shfl_xor_sync(0xffffffffu, p3, off);
            q0 += __shfl_xor_sync(0xffffffffu, q0, off);
            q1 += __shfl_xor_sync(0xffffffffu, q1, off);
            q2 += __shfl_xor_sync(0xffffffffu, q2, off);
            q3 += __shfl_xor_sync(0xffffffffu, q3, off);
        }
        p0 *= LORA_SCALE; p1 *= LORA_SCALE; p2 *= LORA_SCALE; p3 *= LORA_SCALE;
        q0 *= LORA_SCALE; q1 *= LORA_SCALE; q2 *= LORA_SCALE; q3 *= LORA_SCALE;

        // ---- Pass 2: B tile shared between both rows ----
        float4* orow0 = reinterpret_cast<float4*>(out) + row0 * LORA_NF4;
        float4* orow1 = orow0 + LORA_NF4;
        #pragma unroll
        for (int j = 0; j < 8; j++) {
            int idx = j * 32 + lane;
            float4 b0 = sB0[idx];
            float4 b1 = sB1[idx];
            float4 b2 = sB2[idx];
            float4 b3 = sB3[idx];
            float4 o0, o1;
            o0.x = fmaf(p0, b0.x, fmaf(p1, b1.x, fmaf(p2, b2.x, p3 * b3.x)));
            o0.y = fmaf(p0, b0.y, fmaf(p1, b1.y, fmaf(p2, b2.y, p3 * b3.y)));
            o0.z = fmaf(p0, b0.z, fmaf(p1, b1.z, fmaf(p2, b2.z, p3 * b3.z)));
            o0.w = fmaf(p0, b0.w, fmaf(p1, b1.w, fmaf(p2, b2.w, p3 * b3.w)));
            o1.x = fmaf(q0, b0.x, fmaf(q1, b1.x, fmaf(q2, b2.x, q3 * b3.x)));
            o1.y = fmaf(q0, b0.y, fmaf(q1, b1.y, fmaf(q2, b2.y, q3 * b3.y)));
            o1.z = fmaf(q0, b0.z, fmaf(q1, b1.z, fmaf(q2, b2.z, q3 * b3.z)));
            o1.w = fmaf(q0, b0.w, fmaf(q1, b1.w, fmaf(q2, b2.w, q3 * b3.w)));
            __stcs(&orow0[idx], o0);
            __stcs(&orow1[idx], o1);
        }
    }
}

extern "C" void kernel_launch(void* const* d_in, const int* in_sizes, int n_in,
                              void* d_out, int out_size)
{
    const float* x = (const float*)d_in[0];   // [4, 8192, 1024]
    const float* A = (const float*)d_in[1];   // [4, 1024]
    const float* B = (const float*)d_in[2];   // [1024, 4]
    float* out     = (float*)d_out;           // [4, 8192, 1024]

    lora_fused_kernel<<<LORA_GRID, LORA_BLOCK>>>(x, A, B, out);
}